// round 7
// baseline (speedup 1.0000x reference)
#include <cuda_runtime.h>
#include <cuda_fp16.h>
#include <cstdint>
#include <math.h>

#define BSZ   1024
#define TSEQ  64
#define IDIM  64
#define HDIM  1024
#define FUT   16
#define NSTEP (TSEQ + FUT)          // 80
#define G4H   (4 * HDIM)            // 4096
#define OUT_STRIDE (NSTEP * IDIM)   // 5120
#define NBATCH 63                   // deferred-head steps

typedef __half f16;

// ---------------- device scratch (static; no runtime allocation) ----------------
__device__ f16 g_wih1[G4H * IDIM];
__device__ f16 g_whh1[G4H * HDIM];
__device__ f16 g_wih2[G4H * HDIM];
__device__ f16 g_whh2[G4H * HDIM];
__device__ f16 g_wlinp[128 * HDIM];           // W_lin padded to 128 rows (64 real + 64 zero)
__device__ float g_bias1[G4H], g_bias2[G4H];
__device__ float g_blinp[128];                // b_lin padded
__device__ f16 g_x[BSZ * TSEQ * IDIM];
__device__ f16 g_h1[2][BSZ * HDIM];
__device__ f16 g_h2s[(NSTEP + 1) * BSZ * HDIM];  // per-step h2 history (~166 MB)
__device__ float g_c1[BSZ * HDIM], g_c2[BSZ * HDIM];
__device__ f16 g_fb[BSZ * IDIM];              // autoregressive feedback
__device__ float g_part[8 * BSZ * IDIM];      // inline head split-K partials

// ---------------- helpers ----------------
__device__ __forceinline__ uint32_t smem_u32(const void* p) {
    return (uint32_t)__cvta_generic_to_shared(p);
}
__device__ __forceinline__ void cp16(uint32_t dst, const void* src) {
    asm volatile("cp.async.cg.shared.global [%0], [%1], 16;\n" :: "r"(dst), "l"(src));
}
__device__ __forceinline__ void cp_commit() { asm volatile("cp.async.commit_group;\n"); }
template<int N> __device__ __forceinline__ void cp_wait() {
    asm volatile("cp.async.wait_group %0;\n" :: "n"(N));
}
__device__ __forceinline__ void ldsm4(uint32_t* r, uint32_t a) {
    asm volatile("ldmatrix.sync.aligned.m8n8.x4.shared.b16 {%0,%1,%2,%3}, [%4];"
        : "=r"(r[0]), "=r"(r[1]), "=r"(r[2]), "=r"(r[3]) : "r"(a));
}
__device__ __forceinline__ void mma16816(float* d, const uint32_t* a, uint32_t b0, uint32_t b1) {
    asm volatile("mma.sync.aligned.m16n8k16.row.col.f32.f16.f16.f32 "
        "{%0,%1,%2,%3}, {%4,%5,%6,%7}, {%8,%9}, {%0,%1,%2,%3};"
        : "+f"(d[0]), "+f"(d[1]), "+f"(d[2]), "+f"(d[3])
        : "r"(a[0]), "r"(a[1]), "r"(a[2]), "r"(a[3]), "r"(b0), "r"(b1));
}
#define SWZ(x) ((x) ^ (((x) >> 3) & 0x70))

__device__ __forceinline__ float sigm(float x) { return 1.f / (1.f + __expf(-x)); }
__device__ __forceinline__ float tanh_f(float x) { return 2.f / (1.f + __expf(-2.f * x)) - 1.f; }

// ---------------- prepass kernels (3 launches total) ----------------
// prepW: all weight converts/permutes. Flat quad dispatch.
#define QW1 (G4H * HDIM / 4)           // 1048576 quads per big weight
#define QIH1 (G4H * IDIM / 4)          // 65536
#define QLIN (128 * HDIM / 4)          // 32768
__global__ void prepW(const float* __restrict__ whh1, const float* __restrict__ wih2,
                      const float* __restrict__ whh2, const float* __restrict__ wih1,
                      const float* __restrict__ wlin) {
    int q = blockIdx.x * blockDim.x + threadIdx.x;
    if (q < 3 * QW1) {
        const float* src = (q < QW1) ? whh1 : ((q < 2 * QW1) ? wih2 : whh2);
        f16* dst = (q < QW1) ? g_whh1 : ((q < 2 * QW1) ? g_wih2 : g_whh2);
        int e = (q % QW1) * 4;
        int n = e >> 10, k = e & 1023;
        int pn = ((n & 1023) << 2) | (n >> 10);
        float4 v = *(const float4*)(src + e);
        dst[(size_t)pn * 1024 + k + 0] = __float2half(v.x);
        dst[(size_t)pn * 1024 + k + 1] = __float2half(v.y);
        dst[(size_t)pn * 1024 + k + 2] = __float2half(v.z);
        dst[(size_t)pn * 1024 + k + 3] = __float2half(v.w);
    } else if (q < 3 * QW1 + QIH1) {
        int e = (q - 3 * QW1) * 4;
        int n = e >> 6, k = e & 63;
        int pn = ((n & 1023) << 2) | (n >> 10);
        float4 v = *(const float4*)(wih1 + e);
        g_wih1[(size_t)pn * 64 + k + 0] = __float2half(v.x);
        g_wih1[(size_t)pn * 64 + k + 1] = __float2half(v.y);
        g_wih1[(size_t)pn * 64 + k + 2] = __float2half(v.z);
        g_wih1[(size_t)pn * 64 + k + 3] = __float2half(v.w);
    } else {
        int e = (q - 3 * QW1 - QIH1) * 4;        // over 128*1024
        int row = e >> 10;
        if (row < 64) {
            float4 v = *(const float4*)(wlin + e);
            g_wlinp[e + 0] = __float2half(v.x);
            g_wlinp[e + 1] = __float2half(v.y);
            g_wlinp[e + 2] = __float2half(v.z);
            g_wlinp[e + 3] = __float2half(v.w);
        } else {
            f16 z = __float2half(0.f);
            g_wlinp[e + 0] = z; g_wlinp[e + 1] = z; g_wlinp[e + 2] = z; g_wlinp[e + 3] = z;
        }
    }
}
__global__ void prepX(const float* __restrict__ x) {
    size_t e = ((size_t)blockIdx.x * blockDim.x + threadIdx.x) * 4;
    float4 v = *(const float4*)(x + e);
    g_x[e + 0] = __float2half(v.x);
    g_x[e + 1] = __float2half(v.y);
    g_x[e + 2] = __float2half(v.z);
    g_x[e + 3] = __float2half(v.w);
}
__global__ void prepMisc(const float* b1a, const float* b1b,
                         const float* b2a, const float* b2b, const float* blin) {
    int i = blockIdx.x * blockDim.x + threadIdx.x;     // 0 .. BSZ*HDIM-1
    f16 z = __float2half(0.f);
    g_h1[0][i] = z;
    g_h2s[i] = z;                 // step-0 h2 state
    g_c1[i] = 0.f; g_c2[i] = 0.f;
    if (i < BSZ * IDIM) g_fb[i] = z;
    if (i < G4H) {
        int pn = ((i & 1023) << 2) | (i >> 10);
        g_bias1[pn] = b1a[i] + b1b[i];
        g_bias2[pn] = b2a[i] + b2b[i];
    }
    if (i < 128) g_blinp[i] = (i < 64) ? blin[i] : 0.f;
}

// ---------------- main GEMM kernel (fp16 mma.sync) ----------------
// C tile 128(M) x 128(N). Two A phases: nA chunks of (A1,W1), nB of (A2,W2).
// K-chunk = 64 fp16 (128B rows, SW128 swizzle).
// MODE 0: fused LSTM epilogue. MODE 1: batched-head epilogue (out[row, step, col<64]).
#define STAGE 32768   // A 16K | W 16K

template<int MODE>
__global__ void __launch_bounds__(256, 2)
gemm_lstm(const f16* __restrict__ A1, int s1, int nA,
          const f16* __restrict__ A2, int s2, int nB,
          const f16* __restrict__ W1, int w1s,
          const f16* __restrict__ W2, int w2s,
          const float* __restrict__ bias,
          float* __restrict__ cbuf, f16* __restrict__ H,
          float* __restrict__ outp)
{
    extern __shared__ __align__(1024) char smem[];
    const int tid = threadIdx.x;
    const int mBase = blockIdx.y * 128;
    const int nBase = blockIdx.x * 128;
    const uint32_t sb = smem_u32(smem);

    float* sbias = (float*)(smem + 3 * STAGE);
    if (tid < 128) sbias[tid] = bias[nBase + tid];

    const int C = nA + nB;

    auto load_chunk = [&](int c, int st) {
        const f16 *A, *W; int as, ws;
        if (c < nA) { A = A1 + c * 64; as = s1; W = W1 + c * 64; ws = w1s; }
        else        { int d = c - nA;
                      A = A2 + d * 64; as = s2; W = W2 + d * 64; ws = w2s; }
        uint32_t base = sb + st * STAGE;
        #pragma unroll
        for (int j = 0; j < 4; ++j) {
            int o = tid + j * 256; int row = o >> 3; int eo = (o & 7) * 8;
            uint32_t boff = SWZ(row * 128 + eo * 2);
            cp16(base + boff,         A + (size_t)(mBase + row) * as + eo);
            cp16(base + 16384 + boff, W + (size_t)(nBase + row) * ws + eo);
        }
        cp_commit();
    };

    // warp mapping: 8 warps = 4(m) x 2(n); warp tile 32 x 64
    const int w = tid >> 5, l = tid & 31;
    const int wm = (w & 3) * 32, wn = (w >> 2) * 64;

    float acc[2][8][4];
    #pragma unroll
    for (int mt = 0; mt < 2; ++mt)
        #pragma unroll
        for (int nt = 0; nt < 8; ++nt)
            #pragma unroll
            for (int j = 0; j < 4; ++j) acc[mt][nt][j] = 0.f;

    load_chunk(0, 0);
    if (C > 1) load_chunk(1, 1); else cp_commit();
    if (C > 2) load_chunk(2, 2); else cp_commit();

    const int aRowOff[2] = { (wm + 0 * 16 + (l & 15)) << 7, (wm + 1 * 16 + (l & 15)) << 7 };
    const int aColSub = (l >> 4) << 4;                        // 0 or 16
    int wRowOff[4];
    #pragma unroll
    for (int ng = 0; ng < 4; ++ng)
        wRowOff[ng] = (wn + ng * 16 + (l & 7) + (((l >> 4) & 1) << 3)) << 7;
    const int wColSub = ((l >> 3) & 1) << 4;                  // 0 or 16

    for (int c = 0; c < C; ++c) {
        const int st = c % 3;
        cp_wait<2>();
        __syncthreads();

        const uint32_t bA = sb + st * STAGE;
        const uint32_t bW = bA + 16384;

        #pragma unroll
        for (int ks = 0; ks < 4; ++ks) {
            uint32_t af[2][4], wf[4][4];
            #pragma unroll
            for (int mt = 0; mt < 2; ++mt) {
                uint32_t off = SWZ((uint32_t)(aRowOff[mt] + ks * 32 + aColSub));
                ldsm4(af[mt], bA + off);
            }
            #pragma unroll
            for (int ng = 0; ng < 4; ++ng) {
                uint32_t off = SWZ((uint32_t)(wRowOff[ng] + ks * 32 + wColSub));
                ldsm4(wf[ng], bW + off);
            }
            #pragma unroll
            for (int mt = 0; mt < 2; ++mt) {
                #pragma unroll
                for (int ng = 0; ng < 4; ++ng) {
                    mma16816(acc[mt][ng * 2],     af[mt], wf[ng][0], wf[ng][1]);
                    mma16816(acc[mt][ng * 2 + 1], af[mt], wf[ng][2], wf[ng][3]);
                }
            }
        }
        __syncthreads();
        if (c + 3 < C) load_chunk(c + 3, (c + 3) % 3);
        else cp_commit();   // keep group count aligned with wait<2>
    }

    if (MODE == 0) {
        // ---------------- fused LSTM epilogue ----------------
        const int gr = l >> 2;
        const bool odd = l & 1;
        const int q = (l >> 1) & 1;

        #pragma unroll
        for (int mt = 0; mt < 2; ++mt) {
            #pragma unroll
            for (int nt = 0; nt < 8; ++nt) {
                float c0 = acc[mt][nt][0], c1 = acc[mt][nt][1];
                float c2 = acc[mt][nt][2], c3 = acc[mt][nt][3];
                float sx = odd ? c0 : c2;
                float sy = odd ? c1 : c3;
                float rx = __shfl_xor_sync(0xFFFFFFFFu, sx, 1);
                float ry = __shfl_xor_sync(0xFFFFFFFFu, sy, 1);
                float iv, fv, gv, ov;
                if (!odd) { iv = c0; fv = c1; gv = rx; ov = ry; }
                else      { iv = rx; fv = ry; gv = c2; ov = c3; }
                int nn  = wn + nt * 8 + q * 4;           // CTA-local gate-i column
                int row = mBase + wm + mt * 16 + gr + (odd ? 8 : 0);
                float xi = iv + sbias[nn + 0];
                float xf = fv + sbias[nn + 1];
                float xg = gv + sbias[nn + 2];
                float xo = ov + sbias[nn + 3];
                float gi = sigm(xi), gf = sigm(xf), gg = tanh_f(xg), go = sigm(xo);
                int unit = (nBase + nn) >> 2;
                size_t idx = (size_t)row * HDIM + unit;
                float cn = gf * cbuf[idx] + gi * gg;
                cbuf[idx] = cn;
                float hn = go * tanh_f(cn);
                H[idx] = __float2half(hn);
            }
        }
    } else {
        // ---------------- batched head epilogue ----------------
        // global m = step*1024 + batchrow; write out[batchrow, step, col] for col<64
        #pragma unroll
        for (int mt = 0; mt < 2; ++mt) {
            #pragma unroll
            for (int nt = 0; nt < 8; ++nt) {
                int col = wn + nt * 8 + 2 * (l & 3);
                if (col < 64) {
                    int r0 = mBase + wm + mt * 16 + (l >> 2);
                    int r1 = r0 + 8;
                    float v0 = acc[mt][nt][0] + sbias[col];
                    float v1 = acc[mt][nt][1] + sbias[col + 1];
                    float v2 = acc[mt][nt][2] + sbias[col];
                    float v3 = acc[mt][nt][3] + sbias[col + 1];
                    float* p0 = outp + (size_t)(r0 & 1023) * OUT_STRIDE + (r0 >> 10) * IDIM + col;
                    float* p1 = outp + (size_t)(r1 & 1023) * OUT_STRIDE + (r1 >> 10) * IDIM + col;
                    p0[0] = v0; p0[1] = v1;
                    p1[0] = v2; p1[1] = v3;
                }
            }
        }
    }
}

// ---------------- inline head (steps 63..79): fp32 split-K ----------------
__global__ __launch_bounds__(256)
void lin_stage1_kernel(const f16* __restrict__ H, const float* __restrict__ Wlin) {
    __shared__ float Hs[16][68];
    __shared__ float Ws[16][68];

    const int tid = threadIdx.x;
    const int mBase = blockIdx.x * 64;
    const int ks = blockIdx.y;               // 0..7
    const int kBeg = ks * 128;

    const int lr = tid >> 2;
    const int lc = (tid & 3) << 2;
    const int tx = tid & 15;
    const int ty = tid >> 4;

    float acc[4][4];
    #pragma unroll
    for (int i = 0; i < 4; ++i)
        #pragma unroll
        for (int j = 0; j < 4; ++j) acc[i][j] = 0.f;

    for (int k0 = kBeg; k0 < kBeg + 128; k0 += 16) {
        size_t hoff = (size_t)(mBase + lr) * HDIM + k0 + lc;
        const __half2* ph = (const __half2*)(H + hoff);
        float2 h0 = __half22float2(ph[0]);
        float2 h1 = __half22float2(ph[1]);
        Hs[lc + 0][lr] = h0.x; Hs[lc + 1][lr] = h0.y;
        Hs[lc + 2][lr] = h1.x; Hs[lc + 3][lr] = h1.y;
        float4 wv = *reinterpret_cast<const float4*>(&Wlin[(size_t)lr * HDIM + k0 + lc]);
        Ws[lc + 0][lr] = wv.x; Ws[lc + 1][lr] = wv.y;
        Ws[lc + 2][lr] = wv.z; Ws[lc + 3][lr] = wv.w;
        __syncthreads();

        #pragma unroll
        for (int kk = 0; kk < 16; ++kk) {
            float a[4], wv2[4];
            #pragma unroll
            for (int i = 0; i < 4; ++i) a[i] = Hs[kk][ty * 4 + i];
            #pragma unroll
            for (int j = 0; j < 4; ++j) wv2[j] = Ws[kk][tx * 4 + j];
            #pragma unroll
            for (int i = 0; i < 4; ++i)
                #pragma unroll
                for (int j = 0; j < 4; ++j)
                    acc[i][j] = fmaf(a[i], wv2[j], acc[i][j]);
        }
        __syncthreads();
    }

    #pragma unroll
    for (int i = 0; i < 4; ++i) {
        int m = mBase + ty * 4 + i;
        #pragma unroll
        for (int j = 0; j < 4; ++j) {
            int n = tx * 4 + j;
            g_part[(size_t)ks * (BSZ * IDIM) + m * IDIM + n] = acc[i][j];
        }
    }
}

__global__ void lin_stage2_kernel(const float* __restrict__ blin,
                                  float* __restrict__ outp) {
    int idx = blockIdx.x * blockDim.x + threadIdx.x;   // over BSZ*IDIM
    int m = idx >> 6;
    int n = idx & 63;
    float s = blin[n];
    #pragma unroll
    for (int ks = 0; ks < 8; ++ks) s += g_part[ks * (BSZ * IDIM) + idx];
    outp[(size_t)m * OUT_STRIDE + n] = s;
    g_fb[idx] = __float2half(s);
}

// ---------------- host launch ----------------
extern "C" void kernel_launch(void* const* d_in, const int* in_sizes, int n_in,
                              void* d_out, int out_size) {
    const float* x     = (const float*)d_in[0];
    const float* W_ih1 = (const float*)d_in[1];
    const float* W_hh1 = (const float*)d_in[2];
    const float* b_ih1 = (const float*)d_in[3];
    const float* b_hh1 = (const float*)d_in[4];
    const float* W_ih2 = (const float*)d_in[5];
    const float* W_hh2 = (const float*)d_in[6];
    const float* b_ih2 = (const float*)d_in[7];
    const float* b_hh2 = (const float*)d_in[8];
    const float* W_lin = (const float*)d_in[9];
    const float* b_lin = (const float*)d_in[10];
    float* out = (float*)d_out;

    void *wih1, *whh1, *wih2, *whh2, *wlinp, *xh, *h1, *h2s, *c1, *c2, *fb;
    void *bias1, *bias2, *blinp;
    cudaGetSymbolAddress(&wih1, g_wih1);   cudaGetSymbolAddress(&whh1, g_whh1);
    cudaGetSymbolAddress(&wih2, g_wih2);   cudaGetSymbolAddress(&whh2, g_whh2);
    cudaGetSymbolAddress(&wlinp, g_wlinp);
    cudaGetSymbolAddress(&xh, g_x);
    cudaGetSymbolAddress(&h1, g_h1);       cudaGetSymbolAddress(&h2s, g_h2s);
    cudaGetSymbolAddress(&c1, g_c1);       cudaGetSymbolAddress(&c2, g_c2);
    cudaGetSymbolAddress(&fb, g_fb);
    cudaGetSymbolAddress(&bias1, g_bias1); cudaGetSymbolAddress(&bias2, g_bias2);
    cudaGetSymbolAddress(&blinp, g_blinp);

    f16* H1[2] = { (f16*)h1, (f16*)h1 + BSZ * HDIM };
    f16* H2S   = (f16*)h2s;

    constexpr int SMEM_MAIN = 3 * STAGE + 512;   // 98816
    cudaFuncSetAttribute(gemm_lstm<0>, cudaFuncAttributeMaxDynamicSharedMemorySize, SMEM_MAIN);
    cudaFuncSetAttribute(gemm_lstm<1>, cudaFuncAttributeMaxDynamicSharedMemorySize, SMEM_MAIN);

    // ---- prepasses (3 launches; launch idx 3 = first GEMM for ncu) ----
    prepW<<<(3 * QW1 + QIH1 + QLIN) / 256, 256>>>(W_hh1, W_ih2, W_hh2, W_ih1, W_lin);
    prepX<<<(BSZ * TSEQ * IDIM / 4) / 256, 256>>>(x);
    prepMisc<<<(BSZ * HDIM) / 256, 256>>>(b_ih1, b_hh1, b_ih2, b_hh2, b_lin);

    const dim3 gL(G4H / 128, BSZ / 128);   // (32, 8)

    for (int s = 0; s < NSTEP; ++s) {
        int rp = s & 1, wp = rp ^ 1;

        const f16* a1; int s1;
        if (s < TSEQ) { a1 = (const f16*)xh + (size_t)s * IDIM; s1 = TSEQ * IDIM; }
        else          { a1 = (const f16*)fb; s1 = IDIM; }

        // layer 1
        gemm_lstm<0><<<gL, 256, SMEM_MAIN>>>(
            a1, s1, 1,
            H1[rp], HDIM, 16,
            (const f16*)wih1, IDIM,
            (const f16*)whh1, HDIM,
            (const float*)bias1,
            (float*)c1, H1[wp], nullptr);

        // layer 2: h2 state s -> s+1
        gemm_lstm<0><<<gL, 256, SMEM_MAIN>>>(
            H1[wp], HDIM, 16,
            H2S + (size_t)s * BSZ * HDIM, HDIM, 16,
            (const f16*)wih2, HDIM,
            (const f16*)whh2, HDIM,
            (const float*)bias2,
            (float*)c2, H2S + (size_t)(s + 1) * BSZ * HDIM, nullptr);

        // inline head only where feedback is needed (s >= 63)
        if (s >= TSEQ - 1) {
            lin_stage1_kernel<<<dim3(BSZ / 64, 8), 256>>>(
                H2S + (size_t)(s + 1) * BSZ * HDIM, W_lin);
            lin_stage2_kernel<<<(BSZ * IDIM) / 256, 256>>>(b_lin, out + (size_t)s * IDIM);
        }
    }

    // batched head for steps 0..62: one HMMA GEMM over M = 63*1024 rows
    gemm_lstm<1><<<dim3(1, NBATCH * 8), 256, SMEM_MAIN>>>(
        H2S + (size_t)BSZ * HDIM, HDIM, 16,
        nullptr, HDIM, 0,
        (const f16*)wlinp, HDIM,
        nullptr, HDIM,
        (const float*)blinp,
        nullptr, nullptr, out);
}

// round 8
// speedup vs baseline: 1.4075x; 1.4075x over previous
#include <cuda_runtime.h>
#include <cuda_fp16.h>
#include <cstdint>
#include <math.h>

#define BSZ   1024
#define TSEQ  64
#define IDIM  64
#define HDIM  1024
#define FUT   16
#define NSTEP (TSEQ + FUT)          // 80
#define G4H   (4 * HDIM)            // 4096
#define OUT_STRIDE (NSTEP * IDIM)   // 5120
#define NBATCH 63                   // deferred-head steps

typedef __half f16;

// ---------------- device scratch (static; no runtime allocation) ----------------
__device__ f16 g_wih1[G4H * IDIM];
__device__ f16 g_whh1[G4H * HDIM];
__device__ f16 g_wih2[G4H * HDIM];
__device__ f16 g_whh2[G4H * HDIM];
__device__ f16 g_wlinp[128 * HDIM];           // W_lin padded to 128 rows (64 real + 64 zero)
__device__ float g_bias1[G4H], g_bias2[G4H];
__device__ float g_blinp[128];                // b_lin padded
__device__ f16 g_x[BSZ * TSEQ * IDIM];
__device__ f16 g_h1[2][BSZ * HDIM];
__device__ f16 g_h2[2][BSZ * HDIM];           // R6 hot double-buffer (recurrence operands)
__device__ f16 g_h2hist[NBATCH * BSZ * HDIM]; // shadow history for deferred heads (~126 MB)
__device__ float g_c1[BSZ * HDIM], g_c2[BSZ * HDIM];
__device__ f16 g_fb[BSZ * IDIM];              // autoregressive feedback
__device__ float g_part[8 * BSZ * IDIM];      // inline head split-K partials

// ---------------- helpers ----------------
__device__ __forceinline__ uint32_t smem_u32(const void* p) {
    return (uint32_t)__cvta_generic_to_shared(p);
}
__device__ __forceinline__ void cp16(uint32_t dst, const void* src) {
    asm volatile("cp.async.cg.shared.global [%0], [%1], 16;\n" :: "r"(dst), "l"(src));
}
__device__ __forceinline__ void cp_commit() { asm volatile("cp.async.commit_group;\n"); }
template<int N> __device__ __forceinline__ void cp_wait() {
    asm volatile("cp.async.wait_group %0;\n" :: "n"(N));
}
__device__ __forceinline__ void ldsm4(uint32_t* r, uint32_t a) {
    asm volatile("ldmatrix.sync.aligned.m8n8.x4.shared.b16 {%0,%1,%2,%3}, [%4];"
        : "=r"(r[0]), "=r"(r[1]), "=r"(r[2]), "=r"(r[3]) : "r"(a));
}
__device__ __forceinline__ void mma16816(float* d, const uint32_t* a, uint32_t b0, uint32_t b1) {
    asm volatile("mma.sync.aligned.m16n8k16.row.col.f32.f16.f16.f32 "
        "{%0,%1,%2,%3}, {%4,%5,%6,%7}, {%8,%9}, {%0,%1,%2,%3};"
        : "+f"(d[0]), "+f"(d[1]), "+f"(d[2]), "+f"(d[3])
        : "r"(a[0]), "r"(a[1]), "r"(a[2]), "r"(a[3]), "r"(b0), "r"(b1));
}
#define SWZ(x) ((x) ^ (((x) >> 3) & 0x70))

__device__ __forceinline__ float sigm(float x) { return 1.f / (1.f + __expf(-x)); }
__device__ __forceinline__ float tanh_f(float x) { return 2.f / (1.f + __expf(-2.f * x)) - 1.f; }

// ---------------- prepass kernels (3 launches total) ----------------
#define QW1 (G4H * HDIM / 4)           // quads per big weight
#define QIH1 (G4H * IDIM / 4)
#define QLIN (128 * HDIM / 4)
__global__ void prepW(const float* __restrict__ whh1, const float* __restrict__ wih2,
                      const float* __restrict__ whh2, const float* __restrict__ wih1,
                      const float* __restrict__ wlin) {
    int q = blockIdx.x * blockDim.x + threadIdx.x;
    if (q < 3 * QW1) {
        const float* src = (q < QW1) ? whh1 : ((q < 2 * QW1) ? wih2 : whh2);
        f16* dst = (q < QW1) ? g_whh1 : ((q < 2 * QW1) ? g_wih2 : g_whh2);
        int e = (q % QW1) * 4;
        int n = e >> 10, k = e & 1023;
        int pn = ((n & 1023) << 2) | (n >> 10);
        float4 v = *(const float4*)(src + e);
        dst[(size_t)pn * 1024 + k + 0] = __float2half(v.x);
        dst[(size_t)pn * 1024 + k + 1] = __float2half(v.y);
        dst[(size_t)pn * 1024 + k + 2] = __float2half(v.z);
        dst[(size_t)pn * 1024 + k + 3] = __float2half(v.w);
    } else if (q < 3 * QW1 + QIH1) {
        int e = (q - 3 * QW1) * 4;
        int n = e >> 6, k = e & 63;
        int pn = ((n & 1023) << 2) | (n >> 10);
        float4 v = *(const float4*)(wih1 + e);
        g_wih1[(size_t)pn * 64 + k + 0] = __float2half(v.x);
        g_wih1[(size_t)pn * 64 + k + 1] = __float2half(v.y);
        g_wih1[(size_t)pn * 64 + k + 2] = __float2half(v.z);
        g_wih1[(size_t)pn * 64 + k + 3] = __float2half(v.w);
    } else {
        int e = (q - 3 * QW1 - QIH1) * 4;        // over 128*1024
        int row = e >> 10;
        if (row < 64) {
            float4 v = *(const float4*)(wlin + e);
            g_wlinp[e + 0] = __float2half(v.x);
            g_wlinp[e + 1] = __float2half(v.y);
            g_wlinp[e + 2] = __float2half(v.z);
            g_wlinp[e + 3] = __float2half(v.w);
        } else {
            f16 z = __float2half(0.f);
            g_wlinp[e + 0] = z; g_wlinp[e + 1] = z; g_wlinp[e + 2] = z; g_wlinp[e + 3] = z;
        }
    }
}
__global__ void prepX(const float* __restrict__ x) {
    size_t e = ((size_t)blockIdx.x * blockDim.x + threadIdx.x) * 4;
    float4 v = *(const float4*)(x + e);
    g_x[e + 0] = __float2half(v.x);
    g_x[e + 1] = __float2half(v.y);
    g_x[e + 2] = __float2half(v.z);
    g_x[e + 3] = __float2half(v.w);
}
__global__ void prepMisc(const float* b1a, const float* b1b,
                         const float* b2a, const float* b2b, const float* blin) {
    int i = blockIdx.x * blockDim.x + threadIdx.x;     // 0 .. BSZ*HDIM-1
    f16 z = __float2half(0.f);
    g_h1[0][i] = z; g_h2[0][i] = z;
    g_c1[i] = 0.f;  g_c2[i] = 0.f;
    if (i < BSZ * IDIM) g_fb[i] = z;
    if (i < G4H) {
        int pn = ((i & 1023) << 2) | (i >> 10);
        g_bias1[pn] = b1a[i] + b1b[i];
        g_bias2[pn] = b2a[i] + b2b[i];
    }
    if (i < 128) g_blinp[i] = (i < 64) ? blin[i] : 0.f;
}

// ---------------- main GEMM kernel (fp16 mma.sync) ----------------
// C tile 128(M) x 128(N). Two A phases: nA chunks of (A1,W1), nB of (A2,W2).
// K-chunk = 64 fp16 (128B rows, SW128 swizzle).
// MODE 0: fused LSTM epilogue (+ optional shadow h-store into hist).
// MODE 1: batched-head epilogue (out[row & 1023, row >> 10, col<64]).
#define STAGE 32768   // A 16K | W 16K

template<int MODE>
__global__ void __launch_bounds__(256, 2)
gemm_lstm(const f16* __restrict__ A1, int s1, int nA,
          const f16* __restrict__ A2, int s2, int nB,
          const f16* __restrict__ W1, int w1s,
          const f16* __restrict__ W2, int w2s,
          const float* __restrict__ bias,
          float* __restrict__ cbuf, f16* __restrict__ H,
          f16* __restrict__ hist, float* __restrict__ outp)
{
    extern __shared__ __align__(1024) char smem[];
    const int tid = threadIdx.x;
    const int mBase = blockIdx.y * 128;
    const int nBase = blockIdx.x * 128;
    const uint32_t sb = smem_u32(smem);

    float* sbias = (float*)(smem + 3 * STAGE);
    if (tid < 128) sbias[tid] = bias[nBase + tid];

    const int C = nA + nB;

    auto load_chunk = [&](int c, int st) {
        const f16 *A, *W; int as, ws;
        if (c < nA) { A = A1 + c * 64; as = s1; W = W1 + c * 64; ws = w1s; }
        else        { int d = c - nA;
                      A = A2 + d * 64; as = s2; W = W2 + d * 64; ws = w2s; }
        uint32_t base = sb + st * STAGE;
        #pragma unroll
        for (int j = 0; j < 4; ++j) {
            int o = tid + j * 256; int row = o >> 3; int eo = (o & 7) * 8;
            uint32_t boff = SWZ(row * 128 + eo * 2);
            cp16(base + boff,         A + (size_t)(mBase + row) * as + eo);
            cp16(base + 16384 + boff, W + (size_t)(nBase + row) * ws + eo);
        }
        cp_commit();
    };

    // warp mapping: 8 warps = 4(m) x 2(n); warp tile 32 x 64
    const int w = tid >> 5, l = tid & 31;
    const int wm = (w & 3) * 32, wn = (w >> 2) * 64;

    float acc[2][8][4];
    #pragma unroll
    for (int mt = 0; mt < 2; ++mt)
        #pragma unroll
        for (int nt = 0; nt < 8; ++nt)
            #pragma unroll
            for (int j = 0; j < 4; ++j) acc[mt][nt][j] = 0.f;

    load_chunk(0, 0);
    if (C > 1) load_chunk(1, 1); else cp_commit();
    if (C > 2) load_chunk(2, 2); else cp_commit();

    const int aRowOff[2] = { (wm + 0 * 16 + (l & 15)) << 7, (wm + 1 * 16 + (l & 15)) << 7 };
    const int aColSub = (l >> 4) << 4;                        // 0 or 16
    int wRowOff[4];
    #pragma unroll
    for (int ng = 0; ng < 4; ++ng)
        wRowOff[ng] = (wn + ng * 16 + (l & 7) + (((l >> 4) & 1) << 3)) << 7;
    const int wColSub = ((l >> 3) & 1) << 4;                  // 0 or 16

    for (int c = 0; c < C; ++c) {
        const int st = c % 3;
        cp_wait<2>();
        __syncthreads();

        const uint32_t bA = sb + st * STAGE;
        const uint32_t bW = bA + 16384;

        #pragma unroll
        for (int ks = 0; ks < 4; ++ks) {
            uint32_t af[2][4], wf[4][4];
            #pragma unroll
            for (int mt = 0; mt < 2; ++mt) {
                uint32_t off = SWZ((uint32_t)(aRowOff[mt] + ks * 32 + aColSub));
                ldsm4(af[mt], bA + off);
            }
            #pragma unroll
            for (int ng = 0; ng < 4; ++ng) {
                uint32_t off = SWZ((uint32_t)(wRowOff[ng] + ks * 32 + wColSub));
                ldsm4(wf[ng], bW + off);
            }
            #pragma unroll
            for (int mt = 0; mt < 2; ++mt) {
                #pragma unroll
                for (int ng = 0; ng < 4; ++ng) {
                    mma16816(acc[mt][ng * 2],     af[mt], wf[ng][0], wf[ng][1]);
                    mma16816(acc[mt][ng * 2 + 1], af[mt], wf[ng][2], wf[ng][3]);
                }
            }
        }
        __syncthreads();
        if (c + 3 < C) load_chunk(c + 3, (c + 3) % 3);
        else cp_commit();   // keep group count aligned with wait<2>
    }

    if (MODE == 0) {
        // ---------------- fused LSTM epilogue ----------------
        const int gr = l >> 2;
        const bool odd = l & 1;
        const int q = (l >> 1) & 1;

        #pragma unroll
        for (int mt = 0; mt < 2; ++mt) {
            #pragma unroll
            for (int nt = 0; nt < 8; ++nt) {
                float c0 = acc[mt][nt][0], c1 = acc[mt][nt][1];
                float c2 = acc[mt][nt][2], c3 = acc[mt][nt][3];
                float sx = odd ? c0 : c2;
                float sy = odd ? c1 : c3;
                float rx = __shfl_xor_sync(0xFFFFFFFFu, sx, 1);
                float ry = __shfl_xor_sync(0xFFFFFFFFu, sy, 1);
                float iv, fv, gv, ov;
                if (!odd) { iv = c0; fv = c1; gv = rx; ov = ry; }
                else      { iv = rx; fv = ry; gv = c2; ov = c3; }
                int nn  = wn + nt * 8 + q * 4;           // CTA-local gate-i column
                int row = mBase + wm + mt * 16 + gr + (odd ? 8 : 0);
                float xi = iv + sbias[nn + 0];
                float xf = fv + sbias[nn + 1];
                float xg = gv + sbias[nn + 2];
                float xo = ov + sbias[nn + 3];
                float gi = sigm(xi), gf = sigm(xf), gg = tanh_f(xg), go = sigm(xo);
                int unit = (nBase + nn) >> 2;
                size_t idx = (size_t)row * HDIM + unit;
                float cn = gf * cbuf[idx] + gi * gg;
                cbuf[idx] = cn;
                float hn = go * tanh_f(cn);
                f16 hv = __float2half(hn);
                H[idx] = hv;
                if (hist) hist[idx] = hv;      // shadow copy for deferred head
            }
        }
    } else {
        // ---------------- batched head epilogue ----------------
        #pragma unroll
        for (int mt = 0; mt < 2; ++mt) {
            #pragma unroll
            for (int nt = 0; nt < 8; ++nt) {
                int col = wn + nt * 8 + 2 * (l & 3);
                if (col < 64) {
                    int r0 = mBase + wm + mt * 16 + (l >> 2);
                    int r1 = r0 + 8;
                    float v0 = acc[mt][nt][0] + sbias[col];
                    float v1 = acc[mt][nt][1] + sbias[col + 1];
                    float v2 = acc[mt][nt][2] + sbias[col];
                    float v3 = acc[mt][nt][3] + sbias[col + 1];
                    float* p0 = outp + (size_t)(r0 & 1023) * OUT_STRIDE + (r0 >> 10) * IDIM + col;
                    float* p1 = outp + (size_t)(r1 & 1023) * OUT_STRIDE + (r1 >> 10) * IDIM + col;
                    p0[0] = v0; p0[1] = v1;
                    p1[0] = v2; p1[1] = v3;
                }
            }
        }
    }
}

// ---------------- inline head (steps 63..79): fp32 split-K ----------------
__global__ __launch_bounds__(256)
void lin_stage1_kernel(const f16* __restrict__ H, const float* __restrict__ Wlin) {
    __shared__ float Hs[16][68];
    __shared__ float Ws[16][68];

    const int tid = threadIdx.x;
    const int mBase = blockIdx.x * 64;
    const int ks = blockIdx.y;               // 0..7
    const int kBeg = ks * 128;

    const int lr = tid >> 2;
    const int lc = (tid & 3) << 2;
    const int tx = tid & 15;
    const int ty = tid >> 4;

    float acc[4][4];
    #pragma unroll
    for (int i = 0; i < 4; ++i)
        #pragma unroll
        for (int j = 0; j < 4; ++j) acc[i][j] = 0.f;

    for (int k0 = kBeg; k0 < kBeg + 128; k0 += 16) {
        size_t hoff = (size_t)(mBase + lr) * HDIM + k0 + lc;
        const __half2* ph = (const __half2*)(H + hoff);
        float2 h0 = __half22float2(ph[0]);
        float2 h1 = __half22float2(ph[1]);
        Hs[lc + 0][lr] = h0.x; Hs[lc + 1][lr] = h0.y;
        Hs[lc + 2][lr] = h1.x; Hs[lc + 3][lr] = h1.y;
        float4 wv = *reinterpret_cast<const float4*>(&Wlin[(size_t)lr * HDIM + k0 + lc]);
        Ws[lc + 0][lr] = wv.x; Ws[lc + 1][lr] = wv.y;
        Ws[lc + 2][lr] = wv.z; Ws[lc + 3][lr] = wv.w;
        __syncthreads();

        #pragma unroll
        for (int kk = 0; kk < 16; ++kk) {
            float a[4], wv2[4];
            #pragma unroll
            for (int i = 0; i < 4; ++i) a[i] = Hs[kk][ty * 4 + i];
            #pragma unroll
            for (int j = 0; j < 4; ++j) wv2[j] = Ws[kk][tx * 4 + j];
            #pragma unroll
            for (int i = 0; i < 4; ++i)
                #pragma unroll
                for (int j = 0; j < 4; ++j)
                    acc[i][j] = fmaf(a[i], wv2[j], acc[i][j]);
        }
        __syncthreads();
    }

    #pragma unroll
    for (int i = 0; i < 4; ++i) {
        int m = mBase + ty * 4 + i;
        #pragma unroll
        for (int j = 0; j < 4; ++j) {
            int n = tx * 4 + j;
            g_part[(size_t)ks * (BSZ * IDIM) + m * IDIM + n] = acc[i][j];
        }
    }
}

__global__ void lin_stage2_kernel(const float* __restrict__ blin,
                                  float* __restrict__ outp) {
    int idx = blockIdx.x * blockDim.x + threadIdx.x;   // over BSZ*IDIM
    int m = idx >> 6;
    int n = idx & 63;
    float s = blin[n];
    #pragma unroll
    for (int ks = 0; ks < 8; ++ks) s += g_part[ks * (BSZ * IDIM) + idx];
    outp[(size_t)m * OUT_STRIDE + n] = s;
    g_fb[idx] = __float2half(s);
}

// ---------------- host launch ----------------
extern "C" void kernel_launch(void* const* d_in, const int* in_sizes, int n_in,
                              void* d_out, int out_size) {
    const float* x     = (const float*)d_in[0];
    const float* W_ih1 = (const float*)d_in[1];
    const float* W_hh1 = (const float*)d_in[2];
    const float* b_ih1 = (const float*)d_in[3];
    const float* b_hh1 = (const float*)d_in[4];
    const float* W_ih2 = (const float*)d_in[5];
    const float* W_hh2 = (const float*)d_in[6];
    const float* b_ih2 = (const float*)d_in[7];
    const float* b_hh2 = (const float*)d_in[8];
    const float* W_lin = (const float*)d_in[9];
    const float* b_lin = (const float*)d_in[10];
    float* out = (float*)d_out;

    void *wih1, *whh1, *wih2, *whh2, *wlinp, *xh, *h1, *h2, *h2hist, *c1, *c2, *fb;
    void *bias1, *bias2, *blinp;
    cudaGetSymbolAddress(&wih1, g_wih1);   cudaGetSymbolAddress(&whh1, g_whh1);
    cudaGetSymbolAddress(&wih2, g_wih2);   cudaGetSymbolAddress(&whh2, g_whh2);
    cudaGetSymbolAddress(&wlinp, g_wlinp);
    cudaGetSymbolAddress(&xh, g_x);
    cudaGetSymbolAddress(&h1, g_h1);       cudaGetSymbolAddress(&h2, g_h2);
    cudaGetSymbolAddress(&h2hist, g_h2hist);
    cudaGetSymbolAddress(&c1, g_c1);       cudaGetSymbolAddress(&c2, g_c2);
    cudaGetSymbolAddress(&fb, g_fb);
    cudaGetSymbolAddress(&bias1, g_bias1); cudaGetSymbolAddress(&bias2, g_bias2);
    cudaGetSymbolAddress(&blinp, g_blinp);

    f16* H1[2] = { (f16*)h1, (f16*)h1 + BSZ * HDIM };
    f16* H2[2] = { (f16*)h2, (f16*)h2 + BSZ * HDIM };
    f16* HIST  = (f16*)h2hist;

    constexpr int SMEM_MAIN = 3 * STAGE + 512;   // 98816
    cudaFuncSetAttribute(gemm_lstm<0>, cudaFuncAttributeMaxDynamicSharedMemorySize, SMEM_MAIN);
    cudaFuncSetAttribute(gemm_lstm<1>, cudaFuncAttributeMaxDynamicSharedMemorySize, SMEM_MAIN);

    // ---- prepasses (3 launches) ----
    prepW<<<(3 * QW1 + QIH1 + QLIN) / 256, 256>>>(W_hh1, W_ih2, W_hh2, W_ih1, W_lin);
    prepX<<<(BSZ * TSEQ * IDIM / 4) / 256, 256>>>(x);
    prepMisc<<<(BSZ * HDIM) / 256, 256>>>(b_ih1, b_hh1, b_ih2, b_hh2, b_lin);

    const dim3 gL(G4H / 128, BSZ / 128);   // (32, 8)

    for (int s = 0; s < NSTEP; ++s) {
        int rp = s & 1, wp = rp ^ 1;

        const f16* a1; int s1;
        if (s < TSEQ) { a1 = (const f16*)xh + (size_t)s * IDIM; s1 = TSEQ * IDIM; }
        else          { a1 = (const f16*)fb; s1 = IDIM; }

        // layer 1 (identical to R6)
        gemm_lstm<0><<<gL, 256, SMEM_MAIN>>>(
            a1, s1, 1,
            H1[rp], HDIM, 16,
            (const f16*)wih1, IDIM,
            (const f16*)whh1, HDIM,
            (const float*)bias1,
            (float*)c1, H1[wp], nullptr, nullptr);

        // layer 2 (R6 double-buffer semantics + shadow history store for s < 63)
        gemm_lstm<0><<<gL, 256, SMEM_MAIN>>>(
            H1[wp], HDIM, 16,
            H2[rp], HDIM, 16,
            (const f16*)wih2, HDIM,
            (const f16*)whh2, HDIM,
            (const float*)bias2,
            (float*)c2, H2[wp],
            (s < NBATCH) ? HIST + (size_t)s * BSZ * HDIM : nullptr,
            nullptr);

        // inline head only where feedback is needed (s >= 63)
        if (s >= TSEQ - 1) {
            lin_stage1_kernel<<<dim3(BSZ / 64, 8), 256>>>(H2[wp], W_lin);
            lin_stage2_kernel<<<(BSZ * IDIM) / 256, 256>>>(b_lin, out + (size_t)s * IDIM);
        }
    }

    // batched head for steps 0..62: one HMMA GEMM over M = 63*1024 rows
    gemm_lstm<1><<<dim3(1, NBATCH * 8), 256, SMEM_MAIN>>>(
        HIST, HDIM, 16,
        nullptr, HDIM, 0,
        (const f16*)wlinp, HDIM,
        nullptr, HDIM,
        (const float*)blinp,
        nullptr, nullptr, nullptr, out);
}

// round 12
// speedup vs baseline: 1.4212x; 1.0097x over previous
#include <cuda_runtime.h>
#include <cuda_fp16.h>
#include <cstdint>
#include <math.h>

#define BSZ   1024
#define TSEQ  64
#define IDIM  64
#define HDIM  1024
#define FUT   16
#define NSTEP (TSEQ + FUT)          // 80
#define G4H   (4 * HDIM)            // 4096
#define OUT_STRIDE (NSTEP * IDIM)   // 5120
#define NBATCH 63                   // deferred-head steps

typedef __half f16;

// ---------------- device scratch (static; no runtime allocation) ----------------
__device__ f16 g_wih1[G4H * IDIM];
__device__ f16 g_whh1[G4H * HDIM];
__device__ f16 g_wih2[G4H * HDIM];
__device__ f16 g_whh2[G4H * HDIM];
__device__ f16 g_wlinp[128 * HDIM];           // W_lin padded to 128 rows (64 real + 64 zero)
__device__ float g_bias1[G4H], g_bias2[G4H];
__device__ float g_blinp[128];                // b_lin padded
__device__ f16 g_x[BSZ * TSEQ * IDIM];
__device__ f16 g_h1[2][BSZ * HDIM];
__device__ f16 g_h2[2][BSZ * HDIM];           // hot double-buffer (recurrence operands)
__device__ f16 g_h2hist[NBATCH * BSZ * HDIM]; // shadow history for deferred heads (~126 MB)
__device__ float g_c1[BSZ * HDIM], g_c2[BSZ * HDIM];
__device__ f16 g_fb[BSZ * IDIM];              // autoregressive feedback
__device__ float g_part[8 * BSZ * IDIM];      // inline head split-K partials

// ---------------- helpers ----------------
__device__ __forceinline__ uint32_t smem_u32(const void* p) {
    return (uint32_t)__cvta_generic_to_shared(p);
}
__device__ __forceinline__ void cp16(uint32_t dst, const void* src) {
    asm volatile("cp.async.cg.shared.global [%0], [%1], 16;\n" :: "r"(dst), "l"(src));
}
__device__ __forceinline__ void cp_commit() { asm volatile("cp.async.commit_group;\n"); }
template<int N> __device__ __forceinline__ void cp_wait() {
    asm volatile("cp.async.wait_group %0;\n" :: "n"(N));
}
__device__ __forceinline__ void ldsm4(uint32_t* r, uint32_t a) {
    asm volatile("ldmatrix.sync.aligned.m8n8.x4.shared.b16 {%0,%1,%2,%3}, [%4];"
        : "=r"(r[0]), "=r"(r[1]), "=r"(r[2]), "=r"(r[3]) : "r"(a));
}
__device__ __forceinline__ void mma16816(float* d, const uint32_t* a, uint32_t b0, uint32_t b1) {
    asm volatile("mma.sync.aligned.m16n8k16.row.col.f32.f16.f16.f32 "
        "{%0,%1,%2,%3}, {%4,%5,%6,%7}, {%8,%9}, {%0,%1,%2,%3};"
        : "+f"(d[0]), "+f"(d[1]), "+f"(d[2]), "+f"(d[3])
        : "r"(a[0]), "r"(a[1]), "r"(a[2]), "r"(a[3]), "r"(b0), "r"(b1));
}
#define SWZ(x) ((x) ^ (((x) >> 3) & 0x70))

__device__ __forceinline__ float sigm(float x) { return 1.f / (1.f + __expf(-x)); }
__device__ __forceinline__ float tanh_f(float x) { return 2.f / (1.f + __expf(-2.f * x)) - 1.f; }

// ---------------- prepass kernels (3 launches total) ----------------
#define QW1 (G4H * HDIM / 4)           // quads per big weight
#define QIH1 (G4H * IDIM / 4)
#define QLIN (128 * HDIM / 4)
__global__ void prepW(const float* __restrict__ whh1, const float* __restrict__ wih2,
                      const float* __restrict__ whh2, const float* __restrict__ wih1,
                      const float* __restrict__ wlin) {
    int q = blockIdx.x * blockDim.x + threadIdx.x;
    if (q < 3 * QW1) {
        const float* src = (q < QW1) ? whh1 : ((q < 2 * QW1) ? wih2 : whh2);
        f16* dst = (q < QW1) ? g_whh1 : ((q < 2 * QW1) ? g_wih2 : g_whh2);
        int e = (q % QW1) * 4;
        int n = e >> 10, k = e & 1023;
        int pn = ((n & 1023) << 2) | (n >> 10);
        float4 v = *(const float4*)(src + e);
        dst[(size_t)pn * 1024 + k + 0] = __float2half(v.x);
        dst[(size_t)pn * 1024 + k + 1] = __float2half(v.y);
        dst[(size_t)pn * 1024 + k + 2] = __float2half(v.z);
        dst[(size_t)pn * 1024 + k + 3] = __float2half(v.w);
    } else if (q < 3 * QW1 + QIH1) {
        int e = (q - 3 * QW1) * 4;
        int n = e >> 6, k = e & 63;
        int pn = ((n & 1023) << 2) | (n >> 10);
        float4 v = *(const float4*)(wih1 + e);
        g_wih1[(size_t)pn * 64 + k + 0] = __float2half(v.x);
        g_wih1[(size_t)pn * 64 + k + 1] = __float2half(v.y);
        g_wih1[(size_t)pn * 64 + k + 2] = __float2half(v.z);
        g_wih1[(size_t)pn * 64 + k + 3] = __float2half(v.w);
    } else {
        int e = (q - 3 * QW1 - QIH1) * 4;        // over 128*1024
        int row = e >> 10;
        if (row < 64) {
            float4 v = *(const float4*)(wlin + e);
            g_wlinp[e + 0] = __float2half(v.x);
            g_wlinp[e + 1] = __float2half(v.y);
            g_wlinp[e + 2] = __float2half(v.z);
            g_wlinp[e + 3] = __float2half(v.w);
        } else {
            f16 z = __float2half(0.f);
            g_wlinp[e + 0] = z; g_wlinp[e + 1] = z; g_wlinp[e + 2] = z; g_wlinp[e + 3] = z;
        }
    }
}
__global__ void prepX(const float* __restrict__ x) {
    size_t e = ((size_t)blockIdx.x * blockDim.x + threadIdx.x) * 4;
    float4 v = *(const float4*)(x + e);
    g_x[e + 0] = __float2half(v.x);
    g_x[e + 1] = __float2half(v.y);
    g_x[e + 2] = __float2half(v.z);
    g_x[e + 3] = __float2half(v.w);
}
__global__ void prepMisc(const float* b1a, const float* b1b,
                         const float* b2a, const float* b2b, const float* blin) {
    int i = blockIdx.x * blockDim.x + threadIdx.x;     // 0 .. BSZ*HDIM-1
    f16 z = __float2half(0.f);
    g_h1[0][i] = z; g_h2[0][i] = z;
    g_c1[i] = 0.f;  g_c2[i] = 0.f;
    if (i < BSZ * IDIM) g_fb[i] = z;
    if (i < G4H) {
        int pn = ((i & 1023) << 2) | (i >> 10);
        g_bias1[pn] = b1a[i] + b1b[i];
        g_bias2[pn] = b2a[i] + b2b[i];
    }
    if (i < 128) g_blinp[i] = (i < 64) ? blin[i] : 0.f;
}

// ---------------- main GEMM kernel (fp16 mma.sync) ----------------
// C tile 128(M) x 128(N). Two A phases: nA chunks of (A1,W1), nB of (A2,W2).
// K-chunk = 64 fp16 (128B rows, SW128 swizzle).
// Single-barrier 3-stage pipeline (load distance 2): at chunk c, after ONE
// __syncthreads, loads for c+2 go into stage (c+2)%3 == stage last READ at c-1
// (all warps' c-1 ldsm completed before they passed this barrier).
// MODE 0: fused LSTM epilogue (+ optional shadow h-store into hist).
// MODE 1: batched-head epilogue (out[row & 1023, row >> 10, col<64]).
#define STAGE 32768   // A 16K | W 16K

template<int MODE>
__global__ void __launch_bounds__(256, 2)
gemm_lstm(const f16* __restrict__ A1, int s1, int nA,
          const f16* __restrict__ A2, int s2, int nB,
          const f16* __restrict__ W1, int w1s,
          const f16* __restrict__ W2, int w2s,
          const float* __restrict__ bias,
          float* __restrict__ cbuf, f16* __restrict__ H,
          f16* __restrict__ hist, float* __restrict__ outp)
{
    extern __shared__ __align__(1024) char smem[];
    const int tid = threadIdx.x;
    const int mBase = blockIdx.y * 128;
    const int nBase = blockIdx.x * 128;
    const uint32_t sb = smem_u32(smem);

    float* sbias = (float*)(smem + 3 * STAGE);
    if (tid < 128) sbias[tid] = bias[nBase + tid];

    const int C = nA + nB;

    auto load_chunk = [&](int c, int st) {
        const f16 *A, *W; int as, ws;
        if (c < nA) { A = A1 + c * 64; as = s1; W = W1 + c * 64; ws = w1s; }
        else        { int d = c - nA;
                      A = A2 + d * 64; as = s2; W = W2 + d * 64; ws = w2s; }
        uint32_t base = sb + st * STAGE;
        #pragma unroll
        for (int j = 0; j < 4; ++j) {
            int o = tid + j * 256; int row = o >> 3; int eo = (o & 7) * 8;
            uint32_t boff = SWZ(row * 128 + eo * 2);
            cp16(base + boff,         A + (size_t)(mBase + row) * as + eo);
            cp16(base + 16384 + boff, W + (size_t)(nBase + row) * ws + eo);
        }
        cp_commit();
    };

    // warp mapping: 8 warps = 4(m) x 2(n); warp tile 32 x 64
    const int w = tid >> 5, l = tid & 31;
    const int wm = (w & 3) * 32, wn = (w >> 2) * 64;

    float acc[2][8][4];
    #pragma unroll
    for (int mt = 0; mt < 2; ++mt)
        #pragma unroll
        for (int nt = 0; nt < 8; ++nt)
            #pragma unroll
            for (int j = 0; j < 4; ++j) acc[mt][nt][j] = 0.f;

    load_chunk(0, 0);
    if (C > 1) load_chunk(1, 1); else cp_commit();

    const int aRowOff[2] = { (wm + 0 * 16 + (l & 15)) << 7, (wm + 1 * 16 + (l & 15)) << 7 };
    const int aColSub = (l >> 4) << 4;                        // 0 or 16
    int wRowOff[4];
    #pragma unroll
    for (int ng = 0; ng < 4; ++ng)
        wRowOff[ng] = (wn + ng * 16 + (l & 7) + (((l >> 4) & 1) << 3)) << 7;
    const int wColSub = ((l >> 3) & 1) << 4;                  // 0 or 16

    for (int c = 0; c < C; ++c) {
        const int st = c % 3;
        cp_wait<1>();            // chunk c's load complete (c+1 may be in flight)
        __syncthreads();         // single barrier per chunk

        // prefetch chunk c+2 into stage (c+2)%3 (== stage consumed at c-1)
        if (c + 2 < C) load_chunk(c + 2, (c + 2) % 3);
        else cp_commit();        // keep group accounting aligned

        const uint32_t bA = sb + st * STAGE;
        const uint32_t bW = bA + 16384;

        #pragma unroll
        for (int ks = 0; ks < 4; ++ks) {
            uint32_t af[2][4], wf[4][4];
            #pragma unroll
            for (int mt = 0; mt < 2; ++mt) {
                uint32_t off = SWZ((uint32_t)(aRowOff[mt] + ks * 32 + aColSub));
                ldsm4(af[mt], bA + off);
            }
            #pragma unroll
            for (int ng = 0; ng < 4; ++ng) {
                uint32_t off = SWZ((uint32_t)(wRowOff[ng] + ks * 32 + wColSub));
                ldsm4(wf[ng], bW + off);
            }
            #pragma unroll
            for (int mt = 0; mt < 2; ++mt) {
                #pragma unroll
                for (int ng = 0; ng < 4; ++ng) {
                    mma16816(acc[mt][ng * 2],     af[mt], wf[ng][0], wf[ng][1]);
                    mma16816(acc[mt][ng * 2 + 1], af[mt], wf[ng][2], wf[ng][3]);
                }
            }
        }
    }

    if (MODE == 0) {
        // ---------------- fused LSTM epilogue ----------------
        const int gr = l >> 2;
        const bool odd = l & 1;
        const int q = (l >> 1) & 1;

        #pragma unroll
        for (int mt = 0; mt < 2; ++mt) {
            #pragma unroll
            for (int nt = 0; nt < 8; ++nt) {
                float c0 = acc[mt][nt][0], c1 = acc[mt][nt][1];
                float c2 = acc[mt][nt][2], c3 = acc[mt][nt][3];
                float sx = odd ? c0 : c2;
                float sy = odd ? c1 : c3;
                float rx = __shfl_xor_sync(0xFFFFFFFFu, sx, 1);
                float ry = __shfl_xor_sync(0xFFFFFFFFu, sy, 1);
                float iv, fv, gv, ov;
                if (!odd) { iv = c0; fv = c1; gv = rx; ov = ry; }
                else      { iv = rx; fv = ry; gv = c2; ov = c3; }
                int nn  = wn + nt * 8 + q * 4;           // CTA-local gate-i column
                int row = mBase + wm + mt * 16 + gr + (odd ? 8 : 0);
                float xi = iv + sbias[nn + 0];
                float xf = fv + sbias[nn + 1];
                float xg = gv + sbias[nn + 2];
                float xo = ov + sbias[nn + 3];
                float gi = sigm(xi), gf = sigm(xf), gg = tanh_f(xg), go = sigm(xo);
                int unit = (nBase + nn) >> 2;
                size_t idx = (size_t)row * HDIM + unit;
                float cn = gf * cbuf[idx] + gi * gg;
                cbuf[idx] = cn;
                float hn = go * tanh_f(cn);
                f16 hv = __float2half(hn);
                H[idx] = hv;
                if (hist) hist[idx] = hv;      // shadow copy for deferred head
            }
        }
    } else {
        // ---------------- batched head epilogue ----------------
        #pragma unroll
        for (int mt = 0; mt < 2; ++mt) {
            #pragma unroll
            for (int nt = 0; nt < 8; ++nt) {
                int col = wn + nt * 8 + 2 * (l & 3);
                if (col < 64) {
                    int r0 = mBase + wm + mt * 16 + (l >> 2);
                    int r1 = r0 + 8;
                    float v0 = acc[mt][nt][0] + sbias[col];
                    float v1 = acc[mt][nt][1] + sbias[col + 1];
                    float v2 = acc[mt][nt][2] + sbias[col];
                    float v3 = acc[mt][nt][3] + sbias[col + 1];
                    float* p0 = outp + (size_t)(r0 & 1023) * OUT_STRIDE + (r0 >> 10) * IDIM + col;
                    float* p1 = outp + (size_t)(r1 & 1023) * OUT_STRIDE + (r1 >> 10) * IDIM + col;
                    p0[0] = v0; p0[1] = v1;
                    p1[0] = v2; p1[1] = v3;
                }
            }
        }
    }
}

// ---------------- inline head (steps 63..79): fp32 split-K ----------------
__global__ __launch_bounds__(256)
void lin_stage1_kernel(const f16* __restrict__ H, const float* __restrict__ Wlin) {
    __shared__ float Hs[16][68];
    __shared__ float Ws[16][68];

    const int tid = threadIdx.x;
    const int mBase = blockIdx.x * 64;
    const int ks = blockIdx.y;               // 0..7
    const int kBeg = ks * 128;

    const int lr = tid >> 2;
    const int lc = (tid & 3) << 2;
    const int tx = tid & 15;
    const int ty = tid >> 4;

    float acc[4][4];
    #pragma unroll
    for (int i = 0; i < 4; ++i)
        #pragma unroll
        for (int j = 0; j < 4; ++j) acc[i][j] = 0.f;

    for (int k0 = kBeg; k0 < kBeg + 128; k0 += 16) {
        size_t hoff = (size_t)(mBase + lr) * HDIM + k0 + lc;
        const __half2* ph = (const __half2*)(H + hoff);
        float2 h0 = __half22float2(ph[0]);
        float2 h1 = __half22float2(ph[1]);
        Hs[lc + 0][lr] = h0.x; Hs[lc + 1][lr] = h0.y;
        Hs[lc + 2][lr] = h1.x; Hs[lc + 3][lr] = h1.y;
        float4 wv = *reinterpret_cast<const float4*>(&Wlin[(size_t)lr * HDIM + k0 + lc]);
        Ws[lc + 0][lr] = wv.x; Ws[lc + 1][lr] = wv.y;
        Ws[lc + 2][lr] = wv.z; Ws[lc + 3][lr] = wv.w;
        __syncthreads();

        #pragma unroll
        for (int kk = 0; kk < 16; ++kk) {
            float a[4], wv2[4];
            #pragma unroll
            for (int i = 0; i < 4; ++i) a[i] = Hs[kk][ty * 4 + i];
            #pragma unroll
            for (int j = 0; j < 4; ++j) wv2[j] = Ws[kk][tx * 4 + j];
            #pragma unroll
            for (int i = 0; i < 4; ++i)
                #pragma unroll
                for (int j = 0; j < 4; ++j)
                    acc[i][j] = fmaf(a[i], wv2[j], acc[i][j]);
        }
        __syncthreads();
    }

    #pragma unroll
    for (int i = 0; i < 4; ++i) {
        int m = mBase + ty * 4 + i;
        #pragma unroll
        for (int j = 0; j < 4; ++j) {
            int n = tx * 4 + j;
            g_part[(size_t)ks * (BSZ * IDIM) + m * IDIM + n] = acc[i][j];
        }
    }
}

__global__ void lin_stage2_kernel(const float* __restrict__ blin,
                                  float* __restrict__ outp) {
    int idx = blockIdx.x * blockDim.x + threadIdx.x;   // over BSZ*IDIM
    int m = idx >> 6;
    int n = idx & 63;
    float s = blin[n];
    #pragma unroll
    for (int ks = 0; ks < 8; ++ks) s += g_part[ks * (BSZ * IDIM) + idx];
    outp[(size_t)m * OUT_STRIDE + n] = s;
    g_fb[idx] = __float2half(s);
}

// ---------------- host launch ----------------
extern "C" void kernel_launch(void* const* d_in, const int* in_sizes, int n_in,
                              void* d_out, int out_size) {
    const float* x     = (const float*)d_in[0];
    const float* W_ih1 = (const float*)d_in[1];
    const float* W_hh1 = (const float*)d_in[2];
    const float* b_ih1 = (const float*)d_in[3];
    const float* b_hh1 = (const float*)d_in[4];
    const float* W_ih2 = (const float*)d_in[5];
    const float* W_hh2 = (const float*)d_in[6];
    const float* b_ih2 = (const float*)d_in[7];
    const float* b_hh2 = (const float*)d_in[8];
    const float* W_lin = (const float*)d_in[9];
    const float* b_lin = (const float*)d_in[10];
    float* out = (float*)d_out;

    void *wih1, *whh1, *wih2, *whh2, *wlinp, *xh, *h1, *h2, *h2hist, *c1, *c2, *fb;
    void *bias1, *bias2, *blinp;
    cudaGetSymbolAddress(&wih1, g_wih1);   cudaGetSymbolAddress(&whh1, g_whh1);
    cudaGetSymbolAddress(&wih2, g_wih2);   cudaGetSymbolAddress(&whh2, g_whh2);
    cudaGetSymbolAddress(&wlinp, g_wlinp);
    cudaGetSymbolAddress(&xh, g_x);
    cudaGetSymbolAddress(&h1, g_h1);       cudaGetSymbolAddress(&h2, g_h2);
    cudaGetSymbolAddress(&h2hist, g_h2hist);
    cudaGetSymbolAddress(&c1, g_c1);       cudaGetSymbolAddress(&c2, g_c2);
    cudaGetSymbolAddress(&fb, g_fb);
    cudaGetSymbolAddress(&bias1, g_bias1); cudaGetSymbolAddress(&bias2, g_bias2);
    cudaGetSymbolAddress(&blinp, g_blinp);

    f16* H1[2] = { (f16*)h1, (f16*)h1 + BSZ * HDIM };
    f16* H2[2] = { (f16*)h2, (f16*)h2 + BSZ * HDIM };
    f16* HIST  = (f16*)h2hist;

    constexpr int SMEM_MAIN = 3 * STAGE + 512;   // 98816
    cudaFuncSetAttribute(gemm_lstm<0>, cudaFuncAttributeMaxDynamicSharedMemorySize, SMEM_MAIN);
    cudaFuncSetAttribute(gemm_lstm<1>, cudaFuncAttributeMaxDynamicSharedMemorySize, SMEM_MAIN);

    // ---- prepasses (3 launches) ----
    prepW<<<(3 * QW1 + QIH1 + QLIN) / 256, 256>>>(W_hh1, W_ih2, W_hh2, W_ih1, W_lin);
    prepX<<<(BSZ * TSEQ * IDIM / 4) / 256, 256>>>(x);
    prepMisc<<<(BSZ * HDIM) / 256, 256>>>(b_ih1, b_hh1, b_ih2, b_hh2, b_lin);

    const dim3 gL(G4H / 128, BSZ / 128);   // (32, 8)

    for (int s = 0; s < NSTEP; ++s) {
        int rp = s & 1, wp = rp ^ 1;

        const f16* a1; int s1;
        if (s < TSEQ) { a1 = (const f16*)xh + (size_t)s * IDIM; s1 = TSEQ * IDIM; }
        else          { a1 = (const f16*)fb; s1 = IDIM; }

        // layer 1
        gemm_lstm<0><<<gL, 256, SMEM_MAIN>>>(
            a1, s1, 1,
            H1[rp], HDIM, 16,
            (const f16*)wih1, IDIM,
            (const f16*)whh1, HDIM,
            (const float*)bias1,
            (float*)c1, H1[wp], nullptr, nullptr);

        // layer 2 (+ shadow history store for s < 63)
        gemm_lstm<0><<<gL, 256, SMEM_MAIN>>>(
            H1[wp], HDIM, 16,
            H2[rp], HDIM, 16,
            (const f16*)wih2, HDIM,
            (const f16*)whh2, HDIM,
            (const float*)bias2,
            (float*)c2, H2[wp],
            (s < NBATCH) ? HIST + (size_t)s * BSZ * HDIM : nullptr,
            nullptr);

        // inline head only where feedback is needed (s >= 63)
        if (s >= TSEQ - 1) {
            lin_stage1_kernel<<<dim3(BSZ / 64, 8), 256>>>(H2[wp], W_lin);
            lin_stage2_kernel<<<(BSZ * IDIM) / 256, 256>>>(b_lin, out + (size_t)s * IDIM);
        }
    }

    // batched head for steps 0..62: one HMMA GEMM over M = 63*1024 rows
    gemm_lstm<1><<<dim3(1, NBATCH * 8), 256, SMEM_MAIN>>>(
        HIST, HDIM, 16,
        nullptr, HDIM, 0,
        (const f16*)wlinp, HDIM,
        nullptr, HDIM,
        (const float*)blinp,
        nullptr, nullptr, nullptr, out);
}